// round 15
// baseline (speedup 1.0000x reference)
#include <cuda_runtime.h>
#include <cuda_bf16.h>
#include <math.h>

// Problem constants
#define BB 32
#define JJ 512
#define EE 512
#define HH 8
#define MROWS (BB*JJ)          // 16384
#define EPSF 1e-7f

// Scratch (device globals; no allocation allowed). bf16 packed in unsigned.
__device__ unsigned g_qkv_bf[MROWS * 768];    // [16384,1536] bf16  q|k|v
__device__ unsigned g_xt_bf[MROWS * 256];     // x_tan bf16
__device__ unsigned g_vel_bf[MROWS * 256];    // v_tan bf16
__device__ unsigned g_zt_bf[MROWS * 256];     // attn@V bf16 (B,J,E)
__device__ unsigned g_w_bf[655360];           // wqkv | wvproj | wproj words
__device__ float    g_ztan2[MROWS * EE];      // out-proj result fp32
__device__ float2   g_stats[BB * HH * JJ];    // per attn row: (max, 1/sum)

// ---------------------------------------------------------------------------
// helpers
// ---------------------------------------------------------------------------
__device__ __forceinline__ unsigned pk2(float lo, float hi) {
    __nv_bfloat162 t = __floats2bfloat162_rn(lo, hi);
    return *reinterpret_cast<unsigned*>(&t);
}

__device__ __forceinline__ void mma16(float (&c)[4], const unsigned (&a)[4],
                                      const unsigned (&b)[2]) {
    asm volatile(
        "mma.sync.aligned.m16n8k16.row.col.f32.bf16.bf16.f32 "
        "{%0,%1,%2,%3},{%4,%5,%6,%7},{%8,%9},{%0,%1,%2,%3};"
        : "+f"(c[0]), "+f"(c[1]), "+f"(c[2]), "+f"(c[3])
        : "r"(a[0]), "r"(a[1]), "r"(a[2]), "r"(a[3]), "r"(b[0]), "r"(b[1]));
}

__device__ __forceinline__ void cp16(void* smem_dst, const void* gmem_src) {
    unsigned d = (unsigned)__cvta_generic_to_shared(smem_dst);
    asm volatile("cp.async.cg.shared.global [%0], [%1], 16;" :: "r"(d), "l"(gmem_src));
}
__device__ __forceinline__ void cp_commit() { asm volatile("cp.async.commit_group;"); }
__device__ __forceinline__ void cp_wait0() { asm volatile("cp.async.wait_group 0;"); }

__device__ __forceinline__ unsigned s2u(const void* p) {
    return (unsigned)__cvta_generic_to_shared(p);
}
__device__ __forceinline__ void ldm4(unsigned& r0, unsigned& r1, unsigned& r2,
                                     unsigned& r3, unsigned a) {
    asm volatile("ldmatrix.sync.aligned.m8n8.x4.shared.b16 {%0,%1,%2,%3}, [%4];"
                 : "=r"(r0), "=r"(r1), "=r"(r2), "=r"(r3) : "r"(a));
}

// lane offsets for ldmatrix fragments. PITCH = smem row pitch in BYTES.
__device__ __forceinline__ unsigned laneA_off(int lane, int pitch) {
    int sel = lane >> 3;
    return (unsigned)((((sel & 1) * 8) + (lane & 7)) * pitch + (sel >> 1) * 16);
}
__device__ __forceinline__ unsigned laneB_off(int lane, int pitch) {
    int sel = lane >> 3;
    return (unsigned)((((sel >> 1) * 8) + (lane & 7)) * pitch + (sel & 1) * 16);
}

// ---------------------------------------------------------------------------
// fused preprocessing: blocks 0..MROWS-1 do log-map + vel staging (128 thr);
// blocks MROWS.. do weight f32->bf16 conversion (128 words each).
// ---------------------------------------------------------------------------
__global__ void prep_kernel(const float* __restrict__ x, const float* __restrict__ xv,
                            float* __restrict__ xt, unsigned* __restrict__ xtb,
                            unsigned* __restrict__ velb,
                            const float* __restrict__ wqkv, const float* __restrict__ wvp,
                            const float* __restrict__ wpr, unsigned* __restrict__ wout) {
    int blk = blockIdx.x;
    int t = threadIdx.x;  // 128
    if (blk >= MROWS) {
        int i = (blk - MROWS) * 128 + t;   // 0..655359
        const float* src;
        int j;
        if (i < 393216) { src = wqkv; j = i; }
        else if (i < 524288) { src = wvp; j = i - 393216; }
        else { src = wpr; j = i - 524288; }
        float2 f = ((const float2*)src)[j];
        wout[i] = pk2(f.x, f.y);
        return;
    }
    int row = blk;
    const float* p = x + (size_t)row * 513;
    const float* pv = xv + (size_t)row * 513 + 1;
    float* o = xt + (size_t)row * 512;
    __nv_bfloat16* ob = (__nv_bfloat16*)(xtb + (size_t)row * 256);
    __nv_bfloat16* vb = (__nv_bfloat16*)(velb + (size_t)row * 256);
    float v[4];
    float s = 0.f;
#pragma unroll
    for (int q = 0; q < 4; q++) { v[q] = p[1 + t + q * 128]; s += v[q] * v[q]; }
#pragma unroll
    for (int o2 = 16; o2 > 0; o2 >>= 1) s += __shfl_xor_sync(0xffffffffu, s, o2);
    __shared__ float sb[4];
    if ((t & 31) == 0) sb[t >> 5] = s;
    __syncthreads();
    float tot = sb[0] + sb[1] + sb[2] + sb[3];
    float nrm = sqrtf(tot);
    float x0 = fmaxf(p[0], 1.0f + 1e-7f);
    float theta = acoshf(x0);
    float sc = theta / fmaxf(nrm, EPSF);
#pragma unroll
    for (int q = 0; q < 4; q++) {
        float val = sc * v[q];
        o[t + q * 128] = val;
        ob[t + q * 128] = __float2bfloat16(val);
        vb[t + q * 128] = __float2bfloat16(pv[t + q * 128]);
    }
}

// ---------------------------------------------------------------------------
// exp_map0
// ---------------------------------------------------------------------------
__global__ void expmap_kernel(const float* __restrict__ zt, float* __restrict__ zm) {
    int row = blockIdx.x;
    const float* p = zt + (size_t)row * 512;
    float* o = zm + (size_t)row * 513;
    int t = threadIdx.x;
    float v[4];
    float s = 0.f;
#pragma unroll
    for (int q = 0; q < 4; q++) { v[q] = p[t + q * 128]; s += v[q] * v[q]; }
#pragma unroll
    for (int o2 = 16; o2 > 0; o2 >>= 1) s += __shfl_xor_sync(0xffffffffu, s, o2);
    __shared__ float sb[4];
    if ((t & 31) == 0) sb[t >> 5] = s;
    __syncthreads();
    float tot = sb[0] + sb[1] + sb[2] + sb[3];
    float nrm = sqrtf(tot);
    float sc = sinhf(nrm) / fmaxf(nrm, EPSF);
    if (t == 0) o[0] = coshf(nrm);
#pragma unroll
    for (int q = 0; q < 4; q++) o[1 + t + q * 128] = sc * v[q];
}

// ---------------------------------------------------------------------------
// bf16 GEMM, cp.async 2-stage BK=64 + ldmatrix (round-10 winner, exact).
// ---------------------------------------------------------------------------
__global__ void __launch_bounds__(256) gemm_bf(
    const __nv_bfloat16* __restrict__ A1, const __nv_bfloat16* __restrict__ A2,
    const __nv_bfloat16* __restrict__ W1, const __nv_bfloat16* __restrict__ W2,
    int K, int remap,
    unsigned* __restrict__ Cb, int ldcw,
    float* __restrict__ Cf, int ldc, const float* __restrict__ bias) {
    extern __shared__ unsigned gsm[];   // stage s: A at s*9216 words, B at +4608
    int tid = threadIdx.x, lane = tid & 31, w = tid >> 5;
    int gr = lane >> 2, lq = lane & 3;
    int m0w = (w >> 2) * 64, n0w = (w & 3) * 32;
    unsigned lA = laneA_off(lane, 144), lB = laneB_off(lane, 144);
    int arow = blockIdx.y * 128;
    int ncol = blockIdx.x * 128;
    int wrow = (remap && ncol >= 512) ? ncol + 512 : ncol;
    const __nv_bfloat16* A1b = A1 + (size_t)arow * 512;
    const __nv_bfloat16* A2b = A2 + (size_t)arow * 512;
    const __nv_bfloat16* W1b = W1 + (size_t)wrow * 512;
    const __nv_bfloat16* W2b = W2 + (size_t)ncol * 512;
    int lr0 = tid >> 3, lcs = (tid & 7) * 8;

    float c[4][4][4];
#pragma unroll
    for (int i = 0; i < 4; i++)
#pragma unroll
        for (int j = 0; j < 4; j++)
#pragma unroll
            for (int q = 0; q < 4; q++) c[i][j][q] = 0.f;

    int nsteps = K / 64;
    // preload stage 0
    {
        __nv_bfloat16* sA = (__nv_bfloat16*)gsm;
        __nv_bfloat16* sB = (__nv_bfloat16*)(gsm + 4608);
#pragma unroll
        for (int q = 0; q < 4; q++) {
            int r = lr0 + q * 32;
            cp16(sA + r * 72 + lcs, A1b + (size_t)r * 512 + lcs);
            cp16(sB + r * 72 + lcs, W1b + (size_t)r * 512 + lcs);
        }
        cp_commit();
    }

    for (int kstep = 0; kstep < nsteps; kstep++) {
        cp_wait0();
        __syncthreads();
        if (kstep + 1 < nsteps) {
            int k0 = (kstep + 1) * 64;
            const __nv_bfloat16* As = (k0 < 512) ? A1b + k0 : A2b + (k0 - 512);
            const __nv_bfloat16* Ws = (k0 < 512) ? W1b + k0 : W2b + (k0 - 512);
            int st = (kstep + 1) & 1;
            __nv_bfloat16* sA = (__nv_bfloat16*)(gsm + st * 9216);
            __nv_bfloat16* sB = (__nv_bfloat16*)(gsm + st * 9216 + 4608);
#pragma unroll
            for (int q = 0; q < 4; q++) {
                int r = lr0 + q * 32;
                cp16(sA + r * 72 + lcs, As + (size_t)r * 512 + lcs);
                cp16(sB + r * 72 + lcs, Ws + (size_t)r * 512 + lcs);
            }
            cp_commit();
        }
        unsigned Au = s2u(gsm + (kstep & 1) * 9216);
        unsigned Bu = Au + 4608 * 4;
#pragma unroll
        for (int ksh = 0; ksh < 64; ksh += 16) {
            unsigned af[4][4], bf[4][2];
#pragma unroll
            for (int ma = 0; ma < 4; ma++)
                ldm4(af[ma][0], af[ma][1], af[ma][2], af[ma][3],
                     Au + (m0w + ma * 16) * 144 + lA + ksh * 2);
#pragma unroll
            for (int nbp = 0; nbp < 2; nbp++)
                ldm4(bf[2 * nbp][0], bf[2 * nbp][1], bf[2 * nbp + 1][0], bf[2 * nbp + 1][1],
                     Bu + (n0w + nbp * 16) * 144 + lB + ksh * 2);
#pragma unroll
            for (int ma = 0; ma < 4; ma++)
#pragma unroll
                for (int nb = 0; nb < 4; nb++) mma16(c[ma][nb], af[ma], bf[nb]);
        }
    }
    int row0 = arow + m0w;
    int col0 = wrow + n0w;
#pragma unroll
    for (int ma = 0; ma < 4; ma++)
#pragma unroll
        for (int nb = 0; nb < 4; nb++) {
            int r = row0 + ma * 16 + gr;
            int cc = col0 + nb * 8 + 2 * lq;
            if (Cb) {
                Cb[(size_t)r * ldcw + (cc >> 1)] = pk2(c[ma][nb][0], c[ma][nb][1]);
                Cb[(size_t)(r + 8) * ldcw + (cc >> 1)] = pk2(c[ma][nb][2], c[ma][nb][3]);
            } else {
                float2 v0 = make_float2(c[ma][nb][0], c[ma][nb][1]);
                float2 v1 = make_float2(c[ma][nb][2], c[ma][nb][3]);
                float bx = bias[cc], by = bias[cc + 1];
                v0.x += bx; v0.y += by; v1.x += bx; v1.y += by;
                *(float2*)&Cf[(size_t)r * ldc + cc] = v0;
                *(float2*)&Cf[(size_t)(r + 8) * ldc + cc] = v1;
            }
        }
}

// ---------------------------------------------------------------------------
// attention stats: per (64-row q-tile, head), 128 threads = 4 warps.
// (unchanged from round-14 winner)
// ---------------------------------------------------------------------------
__global__ void __launch_bounds__(128) attn_stats(
    const unsigned* __restrict__ qkvb, const float* __restrict__ topo,
    float2* __restrict__ stats) {
    extern __shared__ unsigned sm[];
    unsigned* Qs = sm;                          // 64*36
    unsigned* Kb[2] = {sm + 2304, sm + 2304 + 2304};

    int q0 = blockIdx.x * 64;
    int head = blockIdx.y;
    int b = head >> 3, h = head & 7;
    int tid = threadIdx.x, lane = tid & 31, w = tid >> 5;   // w 0..3
    int lq = lane & 3;
    unsigned lA = laneA_off(lane, 144), lB = laneB_off(lane, 144);
    int gr = lane >> 2;
    int r0 = w * 16 + gr, r1 = r0 + 8;
    const __nv_bfloat16* qkvh = (const __nv_bfloat16*)qkvb;
    const __nv_bfloat16* qbase = qkvh + (size_t)b * 512 * 1536 + h * 64;
    const __nv_bfloat16* kbase = qbase + 512;
    const float scale = 0.125f;
    const float* topo0 = topo + (size_t)(q0 + r0) * 512;
    const float* topo1 = topo + (size_t)(q0 + r1) * 512;

#pragma unroll
    for (int q = 0; q < 8; q++) {
        int i = tid + q * 128;
        int r = i >> 4, c4 = (i & 15) * 4;
        *(uint2*)&Qs[r * 36 + c4 / 2] = *(const uint2*)(qbase + (size_t)(q0 + r) * 1536 + c4);
    }
#pragma unroll
    for (int q = 0; q < 8; q++) {
        int i = tid + q * 128;
        int r = i >> 4, c4 = (i & 15) * 4;
        *(uint2*)&Kb[0][r * 36 + c4 / 2] = *(const uint2*)(kbase + (size_t)r * 1536 + c4);
    }
    __syncthreads();
    unsigned Qu = s2u(Qs) + (w * 16) * 144 + lA;

    float m0 = -1e30f, m1 = -1e30f, s0 = 0.f, s1 = 0.f;
    for (int nc = 0; nc < 8; nc++) {
        unsigned Ku = s2u(Kb[nc & 1]) + lB;
        uint2 kf[8];
        if (nc < 7) {
#pragma unroll
            for (int q = 0; q < 8; q++) {
                int i = tid + q * 128;
                int r = i >> 4, c4 = (i & 15) * 4;
                kf[q] = *(const uint2*)(kbase + (size_t)((nc + 1) * 64 + r) * 1536 + c4);
            }
        }
        float c[8][4];
#pragma unroll
        for (int j = 0; j < 8; j++)
#pragma unroll
            for (int q = 0; q < 4; q++) c[j][q] = 0.f;
#pragma unroll
        for (int ksh = 0; ksh < 64; ksh += 16) {
            unsigned a[4];
            ldm4(a[0], a[1], a[2], a[3], Qu + ksh * 2);
            unsigned bb[8][2];
#pragma unroll
            for (int nbp = 0; nbp < 4; nbp++)
                ldm4(bb[2 * nbp][0], bb[2 * nbp][1], bb[2 * nbp + 1][0], bb[2 * nbp + 1][1],
                     Ku + nbp * 16 * 144 + ksh * 2);
#pragma unroll
            for (int nb = 0; nb < 8; nb++) mma16(c[nb], a, bb[nb]);
        }
        float tm0 = -1e30f, tm1 = -1e30f;
        float v[8][4];
#pragma unroll
        for (int nb = 0; nb < 8; nb++) {
            int gc = nc * 64 + nb * 8 + 2 * lq;
            float2 t0 = *(const float2*)&topo0[gc];
            float2 t1 = *(const float2*)&topo1[gc];
            v[nb][0] = c[nb][0] * scale + t0.x;
            v[nb][1] = c[nb][1] * scale + t0.y;
            v[nb][2] = c[nb][2] * scale + t1.x;
            v[nb][3] = c[nb][3] * scale + t1.y;
            tm0 = fmaxf(tm0, fmaxf(v[nb][0], v[nb][1]));
            tm1 = fmaxf(tm1, fmaxf(v[nb][2], v[nb][3]));
        }
        tm0 = fmaxf(tm0, __shfl_xor_sync(0xffffffffu, tm0, 1));
        tm0 = fmaxf(tm0, __shfl_xor_sync(0xffffffffu, tm0, 2));
        tm1 = fmaxf(tm1, __shfl_xor_sync(0xffffffffu, tm1, 1));
        tm1 = fmaxf(tm1, __shfl_xor_sync(0xffffffffu, tm1, 2));
        float nm0 = fmaxf(m0, tm0), nm1 = fmaxf(m1, tm1);
        float ps0 = 0.f, ps1 = 0.f;
#pragma unroll
        for (int nb = 0; nb < 8; nb++) {
            ps0 += __expf(v[nb][0] - nm0) + __expf(v[nb][1] - nm0);
            ps1 += __expf(v[nb][2] - nm1) + __expf(v[nb][3] - nm1);
        }
        ps0 += __shfl_xor_sync(0xffffffffu, ps0, 1);
        ps0 += __shfl_xor_sync(0xffffffffu, ps0, 2);
        ps1 += __shfl_xor_sync(0xffffffffu, ps1, 1);
        ps1 += __shfl_xor_sync(0xffffffffu, ps1, 2);
        s0 = s0 * __expf(m0 - nm0) + ps0;
        s1 = s1 * __expf(m1 - nm1) + ps1;
        m0 = nm0; m1 = nm1;
        if (nc < 7) {
            unsigned* Kn = Kb[(nc + 1) & 1];
#pragma unroll
            for (int q = 0; q < 8; q++) {
                int i = tid + q * 128;
                int r = i >> 4, c4 = (i & 15) * 4;
                *(uint2*)&Kn[r * 36 + c4 / 2] = kf[q];
            }
        }
        __syncthreads();
    }
    if (lq == 0) {
        stats[(size_t)head * 512 + q0 + r0] = make_float2(m0, 1.0f / s0);
        stats[(size_t)head * 512 + q0 + r1] = make_float2(m1, 1.0f / s1);
    }
}

// ---------------------------------------------------------------------------
// attention main: recompute S, normalize with stats, write attn (streaming),
// PV via register-fragment A + ldmatrix B (V stored transposed [n][k]).
// Block = (128 q-rows, head).
// Dyn smem: Q[128*36] + 2*K[64*36] + 2*V[64*36] = 55296 B
// ---------------------------------------------------------------------------
__global__ void __launch_bounds__(256) attn_main(
    const unsigned* __restrict__ qkvb, const float* __restrict__ topo,
    const float2* __restrict__ stats,
    float* __restrict__ attn, unsigned* __restrict__ ztb) {
    extern __shared__ unsigned sm[];
    unsigned* Qs = sm;                          // 128*36
    unsigned* Kb[2] = {sm + 4608, sm + 4608 + 2304};
    unsigned* Vb[2] = {sm + 9216, sm + 9216 + 2304};   // [n][k] pitch 36w

    int q0 = blockIdx.x * 128;
    int head = blockIdx.y;
    int b = head >> 3, h = head & 7;
    int tid = threadIdx.x, lane = tid & 31, w = tid >> 5;
    int gr = lane >> 2, lq = lane & 3;
    unsigned lA = laneA_off(lane, 144), lB = laneB_off(lane, 144);
    int r0 = w * 16 + gr, r1 = r0 + 8;
    const __nv_bfloat16* qkvh = (const __nv_bfloat16*)qkvb;
    const __nv_bfloat16* qbase = qkvh + (size_t)b * 512 * 1536 + h * 64;
    const __nv_bfloat16* kbase = qbase + 512;
    const __nv_bfloat16* vbase = qbase + 1024;
    const float scale = 0.125f;
    const float* topo0 = topo + (size_t)(q0 + r0) * 512;
    const float* topo1 = topo + (size_t)(q0 + r1) * 512;
    float2 st0 = stats[(size_t)head * 512 + q0 + r0];
    float2 st1 = stats[(size_t)head * 512 + q0 + r1];
    float m0 = st0.x, inv0 = st0.y, m1 = st1.x, inv1 = st1.y;

#pragma unroll
    for (int q = 0; q < 8; q++) {
        int i = tid + q * 256;
        int r = i >> 4, c4 = (i & 15) * 4;
        *(uint2*)&Qs[r * 36 + c4 / 2] = *(const uint2*)(qbase + (size_t)(q0 + r) * 1536 + c4);
    }
#pragma unroll
    for (int q = 0; q < 4; q++) {
        int i = tid + q * 256;
        int r = i >> 4, c4 = (i & 15) * 4;
        *(uint2*)&Kb[0][r * 36 + c4 / 2] = *(const uint2*)(kbase + (size_t)r * 1536 + c4);
    }
    // V[0]: load rows 2kp,2kp+1 (k) x cols n2,n2+1 (n); store transposed [n][k/2]
#pragma unroll
    for (int q = 0; q < 4; q++) {
        int i = tid + q * 256;
        int kp = i >> 5, n2 = (i & 31) * 2;
        unsigned u0 = *(const unsigned*)(vbase + (size_t)(2 * kp) * 1536 + n2);
        unsigned u1 = *(const unsigned*)(vbase + (size_t)(2 * kp + 1) * 1536 + n2);
        Vb[0][n2 * 36 + kp] = __byte_perm(u0, u1, 0x5410);
        Vb[0][(n2 + 1) * 36 + kp] = __byte_perm(u0, u1, 0x7632);
    }
    __syncthreads();
    unsigned Qu = s2u(Qs) + (w * 16) * 144 + lA;

    float z[8][4];
#pragma unroll
    for (int j = 0; j < 8; j++)
#pragma unroll
        for (int q = 0; q < 4; q++) z[j][q] = 0.f;
    float* attn_base = attn + ((size_t)head * 512 + q0) * 512;

    for (int kc = 0; kc < 8; kc++) {
        unsigned Ku = s2u(Kb[kc & 1]) + lB;
        unsigned Vu = s2u(Vb[kc & 1]) + lB;
        uint2 kf[4];
        unsigned vu0[4], vu1[4];
        if (kc < 7) {
#pragma unroll
            for (int q = 0; q < 4; q++) {
                int i = tid + q * 256;
                int r = i >> 4, c4 = (i & 15) * 4;
                kf[q] = *(const uint2*)(kbase + (size_t)((kc + 1) * 64 + r) * 1536 + c4);
            }
#pragma unroll
            for (int q = 0; q < 4; q++) {
                int i = tid + q * 256;
                int kp = i >> 5, n2 = (i & 31) * 2;
                vu0[q] = *(const unsigned*)(vbase + (size_t)((kc + 1) * 64 + 2 * kp) * 1536 + n2);
                vu1[q] = *(const unsigned*)(vbase + (size_t)((kc + 1) * 64 + 2 * kp + 1) * 1536 + n2);
            }
        }
        // recompute S chunk
        float c[8][4];
#pragma unroll
        for (int j = 0; j < 8; j++)
#pragma unroll
            for (int q = 0; q < 4; q++) c[j][q] = 0.f;
#pragma unroll
        for (int ksh = 0; ksh < 64; ksh += 16) {
            unsigned a[4];
            ldm4(a[0], a[1], a[2], a[3], Qu + ksh * 2);
            unsigned bb[8][2];
#pragma unroll
            for (int nbp = 0; nbp < 4; nbp++)
                ldm4(bb[2 * nbp][0], bb[2 * nbp][1], bb[2 * nbp + 1][0], bb[2 * nbp + 1][1],
                     Ku + nbp * 16 * 144 + ksh * 2);
#pragma unroll
            for (int nb = 0; nb < 8; nb++) mma16(c[nb], a, bb[nb]);
        }
        // normalize + write attn (streaming)
#pragma unroll
        for (int nb = 0; nb < 8; nb++) {
            int gc = kc * 64 + nb * 8 + 2 * lq;
            float2 t0 = *(const float2*)&topo0[gc];
            float2 t1 = *(const float2*)&topo1[gc];
            c[nb][0] = __expf(c[nb][0] * scale + t0.x - m0) * inv0;
            c[nb][1] = __expf(c[nb][1] * scale + t0.y - m0) * inv0;
            c[nb][2] = __expf(c[nb][2] * scale + t1.x - m1) * inv1;
            c[nb][3] = __expf(c[nb][3] * scale + t1.y - m1) * inv1;
            __stcs((float2*)&attn_base[(size_t)r0 * 512 + gc], make_float2(c[nb][0], c[nb][1]));
            __stcs((float2*)&attn_base[(size_t)r1 * 512 + gc], make_float2(c[nb][2], c[nb][3]));
        }
        // PV: A-fragments from S accum registers; B-fragments via ldmatrix on V[n][k]
#pragma unroll
        for (int kb = 0; kb < 4; kb++) {
            unsigned pa[4];
            pa[0] = pk2(c[2 * kb][0], c[2 * kb][1]);
            pa[1] = pk2(c[2 * kb][2], c[2 * kb][3]);
            pa[2] = pk2(c[2 * kb + 1][0], c[2 * kb + 1][1]);
            pa[3] = pk2(c[2 * kb + 1][2], c[2 * kb + 1][3]);
            unsigned vb[8][2];
#pragma unroll
            for (int nbp = 0; nbp < 4; nbp++)
                ldm4(vb[2 * nbp][0], vb[2 * nbp][1], vb[2 * nbp + 1][0], vb[2 * nbp + 1][1],
                     Vu + nbp * 16 * 144 + kb * 32);
#pragma unroll
            for (int nb = 0; nb < 8; nb++) mma16(z[nb], pa, vb[nb]);
        }
        if (kc < 7) {
            unsigned* Kn = Kb[(kc + 1) & 1];
            unsigned* Vn = Vb[(kc + 1) & 1];
#pragma unroll
            for (int q = 0; q < 4; q++) {
                int i = tid + q * 256;
                int r = i >> 4, c4 = (i & 15) * 4;
                *(uint2*)&Kn[r * 36 + c4 / 2] = kf[q];
            }
#pragma unroll
            for (int q = 0; q < 4; q++) {
                int i = tid + q * 256;
                int kp = i >> 5, n2 = (i & 31) * 2;
                Vn[n2 * 36 + kp] = __byte_perm(vu0[q], vu1[q], 0x5410);
                Vn[(n2 + 1) * 36 + kp] = __byte_perm(vu0[q], vu1[q], 0x7632);
            }
        }
        __syncthreads();
    }
    int orow = b * 512 + q0 + r0;
#pragma unroll
    for (int nb = 0; nb < 8; nb++) {
        int col = h * 64 + nb * 8 + 2 * lq;
        ztb[(size_t)orow * 256 + (col >> 1)] = pk2(z[nb][0], z[nb][1]);
        ztb[(size_t)(orow + 8) * 256 + (col >> 1)] = pk2(z[nb][2], z[nb][3]);
    }
}

// ---------------------------------------------------------------------------
extern "C" void kernel_launch(void* const* d_in, const int* in_sizes, int n_in,
                              void* d_out, int out_size) {
    const float* x       = (const float*)d_in[0];
    const float* x_vel   = (const float*)d_in[1];
    const float* topo    = (const float*)d_in[2];
    const float* W_qkv   = (const float*)d_in[3];
    const float* W_vproj = (const float*)d_in[4];
    const float* W_proj  = (const float*)d_in[5];
    const float* b_proj  = (const float*)d_in[6];

    float* out    = (float*)d_out;
    float* z_man  = out;                                   // 32*512*513
    float* attn   = out + (size_t)BB * JJ * (EE + 1);      // 32*8*512*512
    float* x_tan  = attn + (size_t)BB * HH * JJ * JJ;      // 32*512*512

    void *pq, *pxt, *pvel, *pzt, *pw, *pz2, *pst;
    cudaGetSymbolAddress(&pq, g_qkv_bf);
    cudaGetSymbolAddress(&pxt, g_xt_bf);
    cudaGetSymbolAddress(&pvel, g_vel_bf);
    cudaGetSymbolAddress(&pzt, g_zt_bf);
    cudaGetSymbolAddress(&pw, g_w_bf);
    cudaGetSymbolAddress(&pz2, g_ztan2);
    cudaGetSymbolAddress(&pst, g_stats);
    unsigned* qkvb = (unsigned*)pq;
    unsigned* xtb  = (unsigned*)pxt;
    unsigned* velb = (unsigned*)pvel;
    unsigned* ztb  = (unsigned*)pzt;
    unsigned* wqkvb   = (unsigned*)pw;
    unsigned* wvprojb = wqkvb + 393216;
    unsigned* wprojb  = wvprojb + 131072;
    float* ztan2 = (float*)pz2;
    float2* stats = (float2*)pst;

    const int gemm_smem = 73728;
    const int stats_smem = 27648;
    const int main_smem = 55296;
    static int attr_set = 0;
    if (!attr_set) {
        cudaFuncSetAttribute(gemm_bf, cudaFuncAttributeMaxDynamicSharedMemorySize, gemm_smem);
        cudaFuncSetAttribute(attn_stats, cudaFuncAttributeMaxDynamicSharedMemorySize, stats_smem);
        cudaFuncSetAttribute(attn_main, cudaFuncAttributeMaxDynamicSharedMemorySize, main_smem);
        attr_set = 1;
    }

    // 1. fused prep: log-map + vel staging + weight conversion
    prep_kernel<<<MROWS + 5120, 128>>>(x, x_vel, x_tan, xtb, velb,
                                       W_qkv, W_vproj, W_proj, wqkvb);

    const __nv_bfloat16* xth = (const __nv_bfloat16*)xtb;
    const __nv_bfloat16* velh = (const __nv_bfloat16*)velb;
    const __nv_bfloat16* wqkvh = (const __nv_bfloat16*)wqkvb;
    const __nv_bfloat16* wvprojh = (const __nv_bfloat16*)wvprojb;
    const __nv_bfloat16* wprojh = (const __nv_bfloat16*)wprojb;
    const __nv_bfloat16* zth = (const __nv_bfloat16*)ztb;

    // 2. q|v slabs (N=1024 remapped), K=512
    {
        dim3 g(8, MROWS / 128);
        gemm_bf<<<g, 256, gemm_smem>>>(xth, xth, wqkvh, wqkvh, 512, 1,
                                       qkvb, 768, nullptr, 0, nullptr);
    }
    // 3. k slab: concat-K (x_tan|v_tan @ Wk|Wvproj), K=1024
    {
        dim3 g(4, MROWS / 128);
        gemm_bf<<<g, 256, gemm_smem>>>(xth, velh, wqkvh + 512 * 512, wvprojh, 1024, 0,
                                       qkvb + 256, 768, nullptr, 0, nullptr);
    }
    // 4. softmax stats
    {
        dim3 g(8, BB * HH);
        attn_stats<<<g, 128, stats_smem>>>(qkvb, topo, stats);
    }
    // 5. attn + PV
    {
        dim3 g(4, BB * HH);
        attn_main<<<g, 256, main_smem>>>(qkvb, topo, stats, attn, ztb);
    }
    // 6. out-proj
    {
        dim3 g(4, MROWS / 128);
        gemm_bf<<<g, 256, gemm_smem>>>(zth, zth, wprojh, wprojh, 512, 0,
                                       nullptr, 0, ztan2, 512, b_proj);
    }
    // 7. exp-map
    expmap_kernel<<<MROWS, 128>>>(ztan2, z_man);
}

// round 16
// speedup vs baseline: 1.5470x; 1.5470x over previous
#include <cuda_runtime.h>
#include <cuda_bf16.h>
#include <math.h>

// Problem constants
#define BB 32
#define JJ 512
#define EE 512
#define HH 8
#define MROWS (BB*JJ)          // 16384
#define EPSF 1e-7f

// Scratch (device globals; no allocation allowed). bf16 packed in unsigned.
__device__ unsigned g_qkv_bf[MROWS * 768];    // [16384,1536] bf16  q|k|v
__device__ unsigned g_xt_bf[MROWS * 256];     // x_tan bf16
__device__ unsigned g_vel_bf[MROWS * 256];    // v_tan bf16
__device__ unsigned g_zt_bf[MROWS * 256];     // attn@V bf16 (B,J,E)
__device__ unsigned g_w_bf[655360];           // wqkv | wvproj | wproj words
__device__ float    g_ztan2[MROWS * EE];      // out-proj result fp32
__device__ float2   g_stats[BB * HH * JJ];    // per attn row: (max, 1/sum)

// ---------------------------------------------------------------------------
// helpers
// ---------------------------------------------------------------------------
__device__ __forceinline__ unsigned pk2(float lo, float hi) {
    __nv_bfloat162 t = __floats2bfloat162_rn(lo, hi);
    return *reinterpret_cast<unsigned*>(&t);
}

__device__ __forceinline__ void mma16(float (&c)[4], const unsigned (&a)[4],
                                      const unsigned (&b)[2]) {
    asm volatile(
        "mma.sync.aligned.m16n8k16.row.col.f32.bf16.bf16.f32 "
        "{%0,%1,%2,%3},{%4,%5,%6,%7},{%8,%9},{%0,%1,%2,%3};"
        : "+f"(c[0]), "+f"(c[1]), "+f"(c[2]), "+f"(c[3])
        : "r"(a[0]), "r"(a[1]), "r"(a[2]), "r"(a[3]), "r"(b[0]), "r"(b[1]));
}

__device__ __forceinline__ void cp16(void* smem_dst, const void* gmem_src) {
    unsigned d = (unsigned)__cvta_generic_to_shared(smem_dst);
    asm volatile("cp.async.cg.shared.global [%0], [%1], 16;" :: "r"(d), "l"(gmem_src));
}
__device__ __forceinline__ void cp_commit() { asm volatile("cp.async.commit_group;"); }
__device__ __forceinline__ void cp_wait0() { asm volatile("cp.async.wait_group 0;"); }

__device__ __forceinline__ unsigned s2u(const void* p) {
    return (unsigned)__cvta_generic_to_shared(p);
}
__device__ __forceinline__ void ldm4(unsigned& r0, unsigned& r1, unsigned& r2,
                                     unsigned& r3, unsigned a) {
    asm volatile("ldmatrix.sync.aligned.m8n8.x4.shared.b16 {%0,%1,%2,%3}, [%4];"
                 : "=r"(r0), "=r"(r1), "=r"(r2), "=r"(r3) : "r"(a));
}

// lane offsets for ldmatrix fragments. PITCH = smem row pitch in BYTES.
__device__ __forceinline__ unsigned laneA_off(int lane, int pitch) {
    int sel = lane >> 3;
    return (unsigned)((((sel & 1) * 8) + (lane & 7)) * pitch + (sel >> 1) * 16);
}
__device__ __forceinline__ unsigned laneB_off(int lane, int pitch) {
    int sel = lane >> 3;
    return (unsigned)((((sel >> 1) * 8) + (lane & 7)) * pitch + (sel & 1) * 16);
}

// ---------------------------------------------------------------------------
// fused preprocessing: blocks 0..MROWS-1 do log-map + vel staging (128 thr);
// blocks MROWS.. do weight f32->bf16 conversion (128 words each).
// ---------------------------------------------------------------------------
__global__ void prep_kernel(const float* __restrict__ x, const float* __restrict__ xv,
                            float* __restrict__ xt, unsigned* __restrict__ xtb,
                            unsigned* __restrict__ velb,
                            const float* __restrict__ wqkv, const float* __restrict__ wvp,
                            const float* __restrict__ wpr, unsigned* __restrict__ wout) {
    int blk = blockIdx.x;
    int t = threadIdx.x;  // 128
    if (blk >= MROWS) {
        int i = (blk - MROWS) * 128 + t;   // 0..655359
        const float* src;
        int j;
        if (i < 393216) { src = wqkv; j = i; }
        else if (i < 524288) { src = wvp; j = i - 393216; }
        else { src = wpr; j = i - 524288; }
        float2 f = ((const float2*)src)[j];
        wout[i] = pk2(f.x, f.y);
        return;
    }
    int row = blk;
    const float* p = x + (size_t)row * 513;
    const float* pv = xv + (size_t)row * 513 + 1;
    float* o = xt + (size_t)row * 512;
    __nv_bfloat16* ob = (__nv_bfloat16*)(xtb + (size_t)row * 256);
    __nv_bfloat16* vb = (__nv_bfloat16*)(velb + (size_t)row * 256);
    float v[4];
    float s = 0.f;
#pragma unroll
    for (int q = 0; q < 4; q++) { v[q] = p[1 + t + q * 128]; s += v[q] * v[q]; }
#pragma unroll
    for (int o2 = 16; o2 > 0; o2 >>= 1) s += __shfl_xor_sync(0xffffffffu, s, o2);
    __shared__ float sb[4];
    if ((t & 31) == 0) sb[t >> 5] = s;
    __syncthreads();
    float tot = sb[0] + sb[1] + sb[2] + sb[3];
    float nrm = sqrtf(tot);
    float x0 = fmaxf(p[0], 1.0f + 1e-7f);
    float theta = acoshf(x0);
    float sc = theta / fmaxf(nrm, EPSF);
#pragma unroll
    for (int q = 0; q < 4; q++) {
        float val = sc * v[q];
        o[t + q * 128] = val;
        ob[t + q * 128] = __float2bfloat16(val);
        vb[t + q * 128] = __float2bfloat16(pv[t + q * 128]);
    }
}

// ---------------------------------------------------------------------------
// exp_map0
// ---------------------------------------------------------------------------
__global__ void expmap_kernel(const float* __restrict__ zt, float* __restrict__ zm) {
    int row = blockIdx.x;
    const float* p = zt + (size_t)row * 512;
    float* o = zm + (size_t)row * 513;
    int t = threadIdx.x;
    float v[4];
    float s = 0.f;
#pragma unroll
    for (int q = 0; q < 4; q++) { v[q] = p[t + q * 128]; s += v[q] * v[q]; }
#pragma unroll
    for (int o2 = 16; o2 > 0; o2 >>= 1) s += __shfl_xor_sync(0xffffffffu, s, o2);
    __shared__ float sb[4];
    if ((t & 31) == 0) sb[t >> 5] = s;
    __syncthreads();
    float tot = sb[0] + sb[1] + sb[2] + sb[3];
    float nrm = sqrtf(tot);
    float sc = sinhf(nrm) / fmaxf(nrm, EPSF);
    if (t == 0) o[0] = coshf(nrm);
#pragma unroll
    for (int q = 0; q < 4; q++) o[1 + t + q * 128] = sc * v[q];
}

// ---------------------------------------------------------------------------
// bf16 GEMM, cp.async 2-stage BK=64 + ldmatrix (round-10 winner, exact).
// C[M,N] = A[M,K]*W[N,K]^T (+bias). Smem rows: 64 halves data, pitch 72
// halves (144 B). Stage = 36864 B; 2 stages = 73728 B.
// ---------------------------------------------------------------------------
__global__ void __launch_bounds__(256) gemm_bf(
    const __nv_bfloat16* __restrict__ A1, const __nv_bfloat16* __restrict__ A2,
    const __nv_bfloat16* __restrict__ W1, const __nv_bfloat16* __restrict__ W2,
    int K, int remap,
    unsigned* __restrict__ Cb, int ldcw,
    float* __restrict__ Cf, int ldc, const float* __restrict__ bias) {
    extern __shared__ unsigned gsm[];   // stage s: A at s*9216 words, B at +4608
    int tid = threadIdx.x, lane = tid & 31, w = tid >> 5;
    int gr = lane >> 2, lq = lane & 3;
    int m0w = (w >> 2) * 64, n0w = (w & 3) * 32;
    unsigned lA = laneA_off(lane, 144), lB = laneB_off(lane, 144);
    int arow = blockIdx.y * 128;
    int ncol = blockIdx.x * 128;
    int wrow = (remap && ncol >= 512) ? ncol + 512 : ncol;
    const __nv_bfloat16* A1b = A1 + (size_t)arow * 512;
    const __nv_bfloat16* A2b = A2 + (size_t)arow * 512;
    const __nv_bfloat16* W1b = W1 + (size_t)wrow * 512;
    const __nv_bfloat16* W2b = W2 + (size_t)ncol * 512;
    int lr0 = tid >> 3, lcs = (tid & 7) * 8;

    float c[4][4][4];
#pragma unroll
    for (int i = 0; i < 4; i++)
#pragma unroll
        for (int j = 0; j < 4; j++)
#pragma unroll
            for (int q = 0; q < 4; q++) c[i][j][q] = 0.f;

    int nsteps = K / 64;
    // preload stage 0
    {
        __nv_bfloat16* sA = (__nv_bfloat16*)gsm;
        __nv_bfloat16* sB = (__nv_bfloat16*)(gsm + 4608);
#pragma unroll
        for (int q = 0; q < 4; q++) {
            int r = lr0 + q * 32;
            cp16(sA + r * 72 + lcs, A1b + (size_t)r * 512 + lcs);
            cp16(sB + r * 72 + lcs, W1b + (size_t)r * 512 + lcs);
        }
        cp_commit();
    }

    for (int kstep = 0; kstep < nsteps; kstep++) {
        cp_wait0();
        __syncthreads();
        if (kstep + 1 < nsteps) {
            int k0 = (kstep + 1) * 64;
            const __nv_bfloat16* As = (k0 < 512) ? A1b + k0 : A2b + (k0 - 512);
            const __nv_bfloat16* Ws = (k0 < 512) ? W1b + k0 : W2b + (k0 - 512);
            int st = (kstep + 1) & 1;
            __nv_bfloat16* sA = (__nv_bfloat16*)(gsm + st * 9216);
            __nv_bfloat16* sB = (__nv_bfloat16*)(gsm + st * 9216 + 4608);
#pragma unroll
            for (int q = 0; q < 4; q++) {
                int r = lr0 + q * 32;
                cp16(sA + r * 72 + lcs, As + (size_t)r * 512 + lcs);
                cp16(sB + r * 72 + lcs, Ws + (size_t)r * 512 + lcs);
            }
            cp_commit();
        }
        unsigned Au = s2u(gsm + (kstep & 1) * 9216);
        unsigned Bu = Au + 4608 * 4;
#pragma unroll
        for (int ksh = 0; ksh < 64; ksh += 16) {
            unsigned af[4][4], bf[4][2];
#pragma unroll
            for (int ma = 0; ma < 4; ma++)
                ldm4(af[ma][0], af[ma][1], af[ma][2], af[ma][3],
                     Au + (m0w + ma * 16) * 144 + lA + ksh * 2);
#pragma unroll
            for (int nbp = 0; nbp < 2; nbp++)
                ldm4(bf[2 * nbp][0], bf[2 * nbp][1], bf[2 * nbp + 1][0], bf[2 * nbp + 1][1],
                     Bu + (n0w + nbp * 16) * 144 + lB + ksh * 2);
#pragma unroll
            for (int ma = 0; ma < 4; ma++)
#pragma unroll
                for (int nb = 0; nb < 4; nb++) mma16(c[ma][nb], af[ma], bf[nb]);
        }
    }
    int row0 = arow + m0w;
    int col0 = wrow + n0w;
#pragma unroll
    for (int ma = 0; ma < 4; ma++)
#pragma unroll
        for (int nb = 0; nb < 4; nb++) {
            int r = row0 + ma * 16 + gr;
            int cc = col0 + nb * 8 + 2 * lq;
            if (Cb) {
                Cb[(size_t)r * ldcw + (cc >> 1)] = pk2(c[ma][nb][0], c[ma][nb][1]);
                Cb[(size_t)(r + 8) * ldcw + (cc >> 1)] = pk2(c[ma][nb][2], c[ma][nb][3]);
            } else {
                float2 v0 = make_float2(c[ma][nb][0], c[ma][nb][1]);
                float2 v1 = make_float2(c[ma][nb][2], c[ma][nb][3]);
                float bx = bias[cc], by = bias[cc + 1];
                v0.x += bx; v0.y += by; v1.x += bx; v1.y += by;
                *(float2*)&Cf[(size_t)r * ldc + cc] = v0;
                *(float2*)&Cf[(size_t)(r + 8) * ldc + cc] = v1;
            }
        }
}

// ---------------------------------------------------------------------------
// attention stats: per (64-row q-tile, head), 128 threads = 4 warps.
// Q/K tiles: 64 halves data per row, pitch 36 words (144 B) -> conflict-free.
// Dyn smem: Q[64*36w] + 2*K[64*36w] = 27648 B.
// ---------------------------------------------------------------------------
__global__ void __launch_bounds__(128) attn_stats(
    const unsigned* __restrict__ qkvb, const float* __restrict__ topo,
    float2* __restrict__ stats) {
    extern __shared__ unsigned sm[];
    unsigned* Qs = sm;                          // 64*36
    unsigned* Kb[2] = {sm + 2304, sm + 2304 + 2304};

    int q0 = blockIdx.x * 64;
    int head = blockIdx.y;
    int b = head >> 3, h = head & 7;
    int tid = threadIdx.x, lane = tid & 31, w = tid >> 5;   // w 0..3
    int lq = lane & 3;
    unsigned lA = laneA_off(lane, 144), lB = laneB_off(lane, 144);
    int gr = lane >> 2;
    int r0 = w * 16 + gr, r1 = r0 + 8;
    const __nv_bfloat16* qkvh = (const __nv_bfloat16*)qkvb;
    const __nv_bfloat16* qbase = qkvh + (size_t)b * 512 * 1536 + h * 64;
    const __nv_bfloat16* kbase = qbase + 512;
    const float scale = 0.125f;
    const float* topo0 = topo + (size_t)(q0 + r0) * 512;
    const float* topo1 = topo + (size_t)(q0 + r1) * 512;

#pragma unroll
    for (int q = 0; q < 8; q++) {
        int i = tid + q * 128;
        int r = i >> 4, c4 = (i & 15) * 4;
        *(uint2*)&Qs[r * 36 + c4 / 2] = *(const uint2*)(qbase + (size_t)(q0 + r) * 1536 + c4);
    }
#pragma unroll
    for (int q = 0; q < 8; q++) {
        int i = tid + q * 128;
        int r = i >> 4, c4 = (i & 15) * 4;
        *(uint2*)&Kb[0][r * 36 + c4 / 2] = *(const uint2*)(kbase + (size_t)r * 1536 + c4);
    }
    __syncthreads();
    unsigned Qu = s2u(Qs) + (w * 16) * 144 + lA;

    float m0 = -1e30f, m1 = -1e30f, s0 = 0.f, s1 = 0.f;
    for (int nc = 0; nc < 8; nc++) {
        unsigned Ku = s2u(Kb[nc & 1]) + lB;
        uint2 kf[8];
        if (nc < 7) {
#pragma unroll
            for (int q = 0; q < 8; q++) {
                int i = tid + q * 128;
                int r = i >> 4, c4 = (i & 15) * 4;
                kf[q] = *(const uint2*)(kbase + (size_t)((nc + 1) * 64 + r) * 1536 + c4);
            }
        }
        float c[8][4];
#pragma unroll
        for (int j = 0; j < 8; j++)
#pragma unroll
            for (int q = 0; q < 4; q++) c[j][q] = 0.f;
#pragma unroll
        for (int ksh = 0; ksh < 64; ksh += 16) {
            unsigned a[4];
            ldm4(a[0], a[1], a[2], a[3], Qu + ksh * 2);
            unsigned bb[8][2];
#pragma unroll
            for (int nbp = 0; nbp < 4; nbp++)
                ldm4(bb[2 * nbp][0], bb[2 * nbp][1], bb[2 * nbp + 1][0], bb[2 * nbp + 1][1],
                     Ku + nbp * 16 * 144 + ksh * 2);
#pragma unroll
            for (int nb = 0; nb < 8; nb++) mma16(c[nb], a, bb[nb]);
        }
        float tm0 = -1e30f, tm1 = -1e30f;
        float v[8][4];
#pragma unroll
        for (int nb = 0; nb < 8; nb++) {
            int gc = nc * 64 + nb * 8 + 2 * lq;
            float2 t0 = *(const float2*)&topo0[gc];
            float2 t1 = *(const float2*)&topo1[gc];
            v[nb][0] = c[nb][0] * scale + t0.x;
            v[nb][1] = c[nb][1] * scale + t0.y;
            v[nb][2] = c[nb][2] * scale + t1.x;
            v[nb][3] = c[nb][3] * scale + t1.y;
            tm0 = fmaxf(tm0, fmaxf(v[nb][0], v[nb][1]));
            tm1 = fmaxf(tm1, fmaxf(v[nb][2], v[nb][3]));
        }
        tm0 = fmaxf(tm0, __shfl_xor_sync(0xffffffffu, tm0, 1));
        tm0 = fmaxf(tm0, __shfl_xor_sync(0xffffffffu, tm0, 2));
        tm1 = fmaxf(tm1, __shfl_xor_sync(0xffffffffu, tm1, 1));
        tm1 = fmaxf(tm1, __shfl_xor_sync(0xffffffffu, tm1, 2));
        float nm0 = fmaxf(m0, tm0), nm1 = fmaxf(m1, tm1);
        float ps0 = 0.f, ps1 = 0.f;
#pragma unroll
        for (int nb = 0; nb < 8; nb++) {
            ps0 += __expf(v[nb][0] - nm0) + __expf(v[nb][1] - nm0);
            ps1 += __expf(v[nb][2] - nm1) + __expf(v[nb][3] - nm1);
        }
        ps0 += __shfl_xor_sync(0xffffffffu, ps0, 1);
        ps0 += __shfl_xor_sync(0xffffffffu, ps0, 2);
        ps1 += __shfl_xor_sync(0xffffffffu, ps1, 1);
        ps1 += __shfl_xor_sync(0xffffffffu, ps1, 2);
        s0 = s0 * __expf(m0 - nm0) + ps0;
        s1 = s1 * __expf(m1 - nm1) + ps1;
        m0 = nm0; m1 = nm1;
        if (nc < 7) {
            unsigned* Kn = Kb[(nc + 1) & 1];
#pragma unroll
            for (int q = 0; q < 8; q++) {
                int i = tid + q * 128;
                int r = i >> 4, c4 = (i & 15) * 4;
                *(uint2*)&Kn[r * 36 + c4 / 2] = kf[q];
            }
        }
        __syncthreads();
    }
    if (lq == 0) {
        stats[(size_t)head * 512 + q0 + r0] = make_float2(m0, 1.0f / s0);
        stats[(size_t)head * 512 + q0 + r1] = make_float2(m1, 1.0f / s1);
    }
}

// ---------------------------------------------------------------------------
// attention main: recompute S, normalize with stats, write attn (streaming),
// PV via register-fragment A + scalar-LDS V path (measured conflict-free).
// Block = (128 q-rows, head).
// Dyn smem: Q[128*36] + 2*K[64*36] + 2*V[32*72] = 55296 B
// ---------------------------------------------------------------------------
__global__ void __launch_bounds__(256) attn_main(
    const unsigned* __restrict__ qkvb, const float* __restrict__ topo,
    const float2* __restrict__ stats,
    float* __restrict__ attn, unsigned* __restrict__ ztb) {
    extern __shared__ unsigned sm[];
    unsigned* Qs = sm;                          // 128*36
    unsigned* Kb[2] = {sm + 4608, sm + 4608 + 2304};
    unsigned* Vb[2] = {sm + 9216, sm + 9216 + 2304};

    int q0 = blockIdx.x * 128;
    int head = blockIdx.y;
    int b = head >> 3, h = head & 7;
    int tid = threadIdx.x, lane = tid & 31, w = tid >> 5;
    int gr = lane >> 2, lq = lane & 3;
    unsigned lA = laneA_off(lane, 144), lB = laneB_off(lane, 144);
    int r0 = w * 16 + gr, r1 = r0 + 8;
    const __nv_bfloat16* qkvh = (const __nv_bfloat16*)qkvb;
    const __nv_bfloat16* qbase = qkvh + (size_t)b * 512 * 1536 + h * 64;
    const __nv_bfloat16* kbase = qbase + 512;
    const __nv_bfloat16* vbase = qbase + 1024;
    const float scale = 0.125f;
    const float* topo0 = topo + (size_t)(q0 + r0) * 512;
    const float* topo1 = topo + (size_t)(q0 + r1) * 512;
    float2 st0 = stats[(size_t)head * 512 + q0 + r0];
    float2 st1 = stats[(size_t)head * 512 + q0 + r1];
    float m0 = st0.x, inv0 = st0.y, m1 = st1.x, inv1 = st1.y;

#pragma unroll
    for (int q = 0; q < 8; q++) {
        int i = tid + q * 256;
        int r = i >> 4, c4 = (i & 15) * 4;
        *(uint2*)&Qs[r * 36 + c4 / 2] = *(const uint2*)(qbase + (size_t)(q0 + r) * 1536 + c4);
    }
#pragma unroll
    for (int q = 0; q < 4; q++) {
        int i = tid + q * 256;
        int r = i >> 4, c4 = (i & 15) * 4;
        *(uint2*)&Kb[0][r * 36 + c4 / 2] = *(const uint2*)(kbase + (size_t)r * 1536 + c4);
    }
#pragma unroll
    for (int q = 0; q < 4; q++) {
        int i = tid + q * 256;
        int kp = i >> 5, n2 = (i & 31) * 2;
        unsigned u0 = *(const unsigned*)(vbase + (size_t)(2 * kp) * 1536 + n2);
        unsigned u1 = *(const unsigned*)(vbase + (size_t)(2 * kp + 1) * 1536 + n2);
        Vb[0][kp * 72 + n2] = __byte_perm(u0, u1, 0x5410);
        Vb[0][kp * 72 + n2 + 1] = __byte_perm(u0, u1, 0x7632);
    }
    __syncthreads();
    unsigned Qu = s2u(Qs) + (w * 16) * 144 + lA;

    float z[8][4];
#pragma unroll
    for (int j = 0; j < 8; j++)
#pragma unroll
        for (int q = 0; q < 4; q++) z[j][q] = 0.f;
    float* attn_base = attn + ((size_t)head * 512 + q0) * 512;

    for (int kc = 0; kc < 8; kc++) {
        unsigned Ku = s2u(Kb[kc & 1]) + lB;
        const unsigned* Vs = Vb[kc & 1];
        uint2 kf[4];
        unsigned vu0[4], vu1[4];
        if (kc < 7) {
#pragma unroll
            for (int q = 0; q < 4; q++) {
                int i = tid + q * 256;
                int r = i >> 4, c4 = (i & 15) * 4;
                kf[q] = *(const uint2*)(kbase + (size_t)((kc + 1) * 64 + r) * 1536 + c4);
            }
#pragma unroll
            for (int q = 0; q < 4; q++) {
                int i = tid + q * 256;
                int kp = i >> 5, n2 = (i & 31) * 2;
                vu0[q] = *(const unsigned*)(vbase + (size_t)((kc + 1) * 64 + 2 * kp) * 1536 + n2);
                vu1[q] = *(const unsigned*)(vbase + (size_t)((kc + 1) * 64 + 2 * kp + 1) * 1536 + n2);
            }
        }
        float c[8][4];
#pragma unroll
        for (int j = 0; j < 8; j++)
#pragma unroll
            for (int q = 0; q < 4; q++) c[j][q] = 0.f;
#pragma unroll
        for (int ksh = 0; ksh < 64; ksh += 16) {
            unsigned a[4];
            ldm4(a[0], a[1], a[2], a[3], Qu + ksh * 2);
            unsigned bb[8][2];
#pragma unroll
            for (int nbp = 0; nbp < 4; nbp++)
                ldm4(bb[2 * nbp][0], bb[2 * nbp][1], bb[2 * nbp + 1][0], bb[2 * nbp + 1][1],
                     Ku + nbp * 16 * 144 + ksh * 2);
#pragma unroll
            for (int nb = 0; nb < 8; nb++) mma16(c[nb], a, bb[nb]);
        }
#pragma unroll
        for (int nb = 0; nb < 8; nb++) {
            int gc = kc * 64 + nb * 8 + 2 * lq;
            float2 t0 = *(const float2*)&topo0[gc];
            float2 t1 = *(const float2*)&topo1[gc];
            c[nb][0] = __expf(c[nb][0] * scale + t0.x - m0) * inv0;
            c[nb][1] = __expf(c[nb][1] * scale + t0.y - m0) * inv0;
            c[nb][2] = __expf(c[nb][2] * scale + t1.x - m1) * inv1;
            c[nb][3] = __expf(c[nb][3] * scale + t1.y - m1) * inv1;
            __stcs((float2*)&attn_base[(size_t)r0 * 512 + gc], make_float2(c[nb][0], c[nb][1]));
            __stcs((float2*)&attn_base[(size_t)r1 * 512 + gc], make_float2(c[nb][2], c[nb][3]));
        }
#pragma unroll
        for (int kb = 0; kb < 4; kb++) {
            unsigned pa[4];
            pa[0] = pk2(c[2 * kb][0], c[2 * kb][1]);
            pa[1] = pk2(c[2 * kb][2], c[2 * kb][3]);
            pa[2] = pk2(c[2 * kb + 1][0], c[2 * kb + 1][1]);
            pa[3] = pk2(c[2 * kb + 1][2], c[2 * kb + 1][3]);
            int kw = kb * 8;
#pragma unroll
            for (int nb = 0; nb < 8; nb++) {
                int n = nb * 8 + gr;
                unsigned bb[2];
                bb[0] = Vs[(kw + lq) * 72 + n];
                bb[1] = Vs[(kw + lq + 4) * 72 + n];
                mma16(z[nb], pa, bb);
            }
        }
        if (kc < 7) {
            unsigned* Kn = Kb[(kc + 1) & 1];
            unsigned* Vn = Vb[(kc + 1) & 1];
#pragma unroll
            for (int q = 0; q < 4; q++) {
                int i = tid + q * 256;
                int r = i >> 4, c4 = (i & 15) * 4;
                *(uint2*)&Kn[r * 36 + c4 / 2] = kf[q];
            }
#pragma unroll
            for (int q = 0; q < 4; q++) {
                int i = tid + q * 256;
                int kp = i >> 5, n2 = (i & 31) * 2;
                Vn[kp * 72 + n2] = __byte_perm(vu0[q], vu1[q], 0x5410);
                Vn[kp * 72 + n2 + 1] = __byte_perm(vu0[q], vu1[q], 0x7632);
            }
        }
        __syncthreads();
    }
    int orow = b * 512 + q0 + r0;
#pragma unroll
    for (int nb = 0; nb < 8; nb++) {
        int col = h * 64 + nb * 8 + 2 * lq;
        ztb[(size_t)orow * 256 + (col >> 1)] = pk2(z[nb][0], z[nb][1]);
        ztb[(size_t)(orow + 8) * 256 + (col >> 1)] = pk2(z[nb][2], z[nb][3]);
    }
}

// ---------------------------------------------------------------------------
extern "C" void kernel_launch(void* const* d_in, const int* in_sizes, int n_in,
                              void* d_out, int out_size) {
    const float* x       = (const float*)d_in[0];
    const float* x_vel   = (const float*)d_in[1];
    const float* topo    = (const float*)d_in[2];
    const float* W_qkv   = (const float*)d_in[3];
    const float* W_vproj = (const float*)d_in[4];
    const float* W_proj  = (const float*)d_in[5];
    const float* b_proj  = (const float*)d_in[6];

    float* out    = (float*)d_out;
    float* z_man  = out;                                   // 32*512*513
    float* attn   = out + (size_t)BB * JJ * (EE + 1);      // 32*8*512*512
    float* x_tan  = attn + (size_t)BB * HH * JJ * JJ;      // 32*512*512

    void *pq, *pxt, *pvel, *pzt, *pw, *pz2, *pst;
    cudaGetSymbolAddress(&pq, g_qkv_bf);
    cudaGetSymbolAddress(&pxt, g_xt_bf);
    cudaGetSymbolAddress(&pvel, g_vel_bf);
    cudaGetSymbolAddress(&pzt, g_zt_bf);
    cudaGetSymbolAddress(&pw, g_w_bf);
    cudaGetSymbolAddress(&pz2, g_ztan2);
    cudaGetSymbolAddress(&pst, g_stats);
    unsigned* qkvb = (unsigned*)pq;
    unsigned* xtb  = (unsigned*)pxt;
    unsigned* velb = (unsigned*)pvel;
    unsigned* ztb  = (unsigned*)pzt;
    unsigned* wqkvb   = (unsigned*)pw;
    unsigned* wvprojb = wqkvb + 393216;
    unsigned* wprojb  = wvprojb + 131072;
    float* ztan2 = (float*)pz2;
    float2* stats = (float2*)pst;

    const int gemm_smem = 73728;
    const int stats_smem = 27648;
    const int main_smem = 55296;
    static int attr_set = 0;
    if (!attr_set) {
        cudaFuncSetAttribute(gemm_bf, cudaFuncAttributeMaxDynamicSharedMemorySize, gemm_smem);
        cudaFuncSetAttribute(attn_stats, cudaFuncAttributeMaxDynamicSharedMemorySize, stats_smem);
        cudaFuncSetAttribute(attn_main, cudaFuncAttributeMaxDynamicSharedMemorySize, main_smem);
        attr_set = 1;
    }

    // 1. fused prep: log-map + vel staging + weight conversion
    prep_kernel<<<MROWS + 5120, 128>>>(x, x_vel, x_tan, xtb, velb,
                                       W_qkv, W_vproj, W_proj, wqkvb);

    const __nv_bfloat16* xth = (const __nv_bfloat16*)xtb;
    const __nv_bfloat16* velh = (const __nv_bfloat16*)velb;
    const __nv_bfloat16* wqkvh = (const __nv_bfloat16*)wqkvb;
    const __nv_bfloat16* wvprojh = (const __nv_bfloat16*)wvprojb;
    const __nv_bfloat16* wprojh = (const __nv_bfloat16*)wprojb;
    const __nv_bfloat16* zth = (const __nv_bfloat16*)ztb;

    // 2. q|v slabs (N=1024 remapped), K=512
    {
        dim3 g(8, MROWS / 128);
        gemm_bf<<<g, 256, gemm_smem>>>(xth, xth, wqkvh, wqkvh, 512, 1,
                                       qkvb, 768, nullptr, 0, nullptr);
    }
    // 3. k slab: concat-K (x_tan|v_tan @ Wk|Wvproj), K=1024
    {
        dim3 g(4, MROWS / 128);
        gemm_bf<<<g, 256, gemm_smem>>>(xth, velh, wqkvh + 512 * 512, wvprojh, 1024, 0,
                                       qkvb + 256, 768, nullptr, 0, nullptr);
    }
    // 4. softmax stats
    {
        dim3 g(8, BB * HH);
        attn_stats<<<g, 128, stats_smem>>>(qkvb, topo, stats);
    }
    // 5. attn + PV
    {
        dim3 g(4, BB * HH);
        attn_main<<<g, 256, main_smem>>>(qkvb, topo, stats, attn, ztb);
    }
    // 6. out-proj
    {
        dim3 g(4, MROWS / 128);
        gemm_bf<<<g, 256, gemm_smem>>>(zth, zth, wprojh, wprojh, 512, 0,
                                       nullptr, 0, ztan2, 512, b_proj);
    }
    // 7. exp-map
    expmap_kernel<<<MROWS, 128>>>(ztan2, z_man);
}

// round 17
// speedup vs baseline: 1.6001x; 1.0343x over previous
#include <cuda_runtime.h>
#include <cuda_bf16.h>
#include <math.h>

// Problem constants
#define BB 32
#define JJ 512
#define EE 512
#define HH 8
#define MROWS (BB*JJ)          // 16384
#define EPSF 1e-7f

// Scratch (device globals; no allocation allowed). bf16 packed in unsigned.
__device__ unsigned g_qkv_bf[MROWS * 768];    // [16384,1536] bf16  q|k|v
__device__ unsigned g_xt_bf[MROWS * 256];     // x_tan bf16
__device__ unsigned g_vel_bf[MROWS * 256];    // v_tan bf16
__device__ unsigned g_zt_bf[MROWS * 256];     // attn@V bf16 (B,J,E)
__device__ unsigned g_w_bf[655360];           // wqkv | wvproj | wproj words
__device__ float    g_ztan2[MROWS * EE];      // out-proj result fp32
__device__ float2   g_stats[BB * HH * JJ];    // per attn row: (max, 1/sum)

// ---------------------------------------------------------------------------
// helpers
// ---------------------------------------------------------------------------
__device__ __forceinline__ unsigned pk2(float lo, float hi) {
    __nv_bfloat162 t = __floats2bfloat162_rn(lo, hi);
    return *reinterpret_cast<unsigned*>(&t);
}

__device__ __forceinline__ void mma16(float (&c)[4], const unsigned (&a)[4],
                                      const unsigned (&b)[2]) {
    asm volatile(
        "mma.sync.aligned.m16n8k16.row.col.f32.bf16.bf16.f32 "
        "{%0,%1,%2,%3},{%4,%5,%6,%7},{%8,%9},{%0,%1,%2,%3};"
        : "+f"(c[0]), "+f"(c[1]), "+f"(c[2]), "+f"(c[3])
        : "r"(a[0]), "r"(a[1]), "r"(a[2]), "r"(a[3]), "r"(b[0]), "r"(b[1]));
}

__device__ __forceinline__ void cp16(void* smem_dst, const void* gmem_src) {
    unsigned d = (unsigned)__cvta_generic_to_shared(smem_dst);
    asm volatile("cp.async.cg.shared.global [%0], [%1], 16;" :: "r"(d), "l"(gmem_src));
}
__device__ __forceinline__ void cp_commit() { asm volatile("cp.async.commit_group;"); }
__device__ __forceinline__ void cp_wait0() { asm volatile("cp.async.wait_group 0;"); }

__device__ __forceinline__ unsigned s2u(const void* p) {
    return (unsigned)__cvta_generic_to_shared(p);
}
__device__ __forceinline__ void ldm4(unsigned& r0, unsigned& r1, unsigned& r2,
                                     unsigned& r3, unsigned a) {
    asm volatile("ldmatrix.sync.aligned.m8n8.x4.shared.b16 {%0,%1,%2,%3}, [%4];"
                 : "=r"(r0), "=r"(r1), "=r"(r2), "=r"(r3) : "r"(a));
}
__device__ __forceinline__ void ldm4t(unsigned& r0, unsigned& r1, unsigned& r2,
                                      unsigned& r3, unsigned a) {
    asm volatile("ldmatrix.sync.aligned.m8n8.x4.trans.shared.b16 {%0,%1,%2,%3}, [%4];"
                 : "=r"(r0), "=r"(r1), "=r"(r2), "=r"(r3) : "r"(a));
}

// lane offsets for ldmatrix fragments. PITCH = smem row pitch in BYTES.
__device__ __forceinline__ unsigned laneA_off(int lane, int pitch) {
    int sel = lane >> 3;
    return (unsigned)((((sel & 1) * 8) + (lane & 7)) * pitch + (sel >> 1) * 16);
}
__device__ __forceinline__ unsigned laneB_off(int lane, int pitch) {
    int sel = lane >> 3;
    return (unsigned)((((sel >> 1) * 8) + (lane & 7)) * pitch + (sel & 1) * 16);
}

// ---------------------------------------------------------------------------
// fused preprocessing: blocks 0..MROWS-1 do log-map + vel staging (128 thr);
// blocks MROWS.. do weight f32->bf16 conversion (128 words each).
// ---------------------------------------------------------------------------
__global__ void prep_kernel(const float* __restrict__ x, const float* __restrict__ xv,
                            float* __restrict__ xt, unsigned* __restrict__ xtb,
                            unsigned* __restrict__ velb,
                            const float* __restrict__ wqkv, const float* __restrict__ wvp,
                            const float* __restrict__ wpr, unsigned* __restrict__ wout) {
    int blk = blockIdx.x;
    int t = threadIdx.x;  // 128
    if (blk >= MROWS) {
        int i = (blk - MROWS) * 128 + t;   // 0..655359
        const float* src;
        int j;
        if (i < 393216) { src = wqkv; j = i; }
        else if (i < 524288) { src = wvp; j = i - 393216; }
        else { src = wpr; j = i - 524288; }
        float2 f = ((const float2*)src)[j];
        wout[i] = pk2(f.x, f.y);
        return;
    }
    int row = blk;
    const float* p = x + (size_t)row * 513;
    const float* pv = xv + (size_t)row * 513 + 1;
    float* o = xt + (size_t)row * 512;
    __nv_bfloat16* ob = (__nv_bfloat16*)(xtb + (size_t)row * 256);
    __nv_bfloat16* vb = (__nv_bfloat16*)(velb + (size_t)row * 256);
    float v[4];
    float s = 0.f;
#pragma unroll
    for (int q = 0; q < 4; q++) { v[q] = p[1 + t + q * 128]; s += v[q] * v[q]; }
#pragma unroll
    for (int o2 = 16; o2 > 0; o2 >>= 1) s += __shfl_xor_sync(0xffffffffu, s, o2);
    __shared__ float sb[4];
    if ((t & 31) == 0) sb[t >> 5] = s;
    __syncthreads();
    float tot = sb[0] + sb[1] + sb[2] + sb[3];
    float nrm = sqrtf(tot);
    float x0 = fmaxf(p[0], 1.0f + 1e-7f);
    float theta = acoshf(x0);
    float sc = theta / fmaxf(nrm, EPSF);
#pragma unroll
    for (int q = 0; q < 4; q++) {
        float val = sc * v[q];
        o[t + q * 128] = val;
        ob[t + q * 128] = __float2bfloat16(val);
        vb[t + q * 128] = __float2bfloat16(pv[t + q * 128]);
    }
}

// ---------------------------------------------------------------------------
// exp_map0
// ---------------------------------------------------------------------------
__global__ void expmap_kernel(const float* __restrict__ zt, float* __restrict__ zm) {
    int row = blockIdx.x;
    const float* p = zt + (size_t)row * 512;
    float* o = zm + (size_t)row * 513;
    int t = threadIdx.x;
    float v[4];
    float s = 0.f;
#pragma unroll
    for (int q = 0; q < 4; q++) { v[q] = p[t + q * 128]; s += v[q] * v[q]; }
#pragma unroll
    for (int o2 = 16; o2 > 0; o2 >>= 1) s += __shfl_xor_sync(0xffffffffu, s, o2);
    __shared__ float sb[4];
    if ((t & 31) == 0) sb[t >> 5] = s;
    __syncthreads();
    float tot = sb[0] + sb[1] + sb[2] + sb[3];
    float nrm = sqrtf(tot);
    float sc = sinhf(nrm) / fmaxf(nrm, EPSF);
    if (t == 0) o[0] = coshf(nrm);
#pragma unroll
    for (int q = 0; q < 4; q++) o[1 + t + q * 128] = sc * v[q];
}

// ---------------------------------------------------------------------------
// bf16 GEMM, cp.async 2-stage BK=64 + ldmatrix (round-10 winner, exact).
// ---------------------------------------------------------------------------
__global__ void __launch_bounds__(256) gemm_bf(
    const __nv_bfloat16* __restrict__ A1, const __nv_bfloat16* __restrict__ A2,
    const __nv_bfloat16* __restrict__ W1, const __nv_bfloat16* __restrict__ W2,
    int K, int remap,
    unsigned* __restrict__ Cb, int ldcw,
    float* __restrict__ Cf, int ldc, const float* __restrict__ bias) {
    extern __shared__ unsigned gsm[];   // stage s: A at s*9216 words, B at +4608
    int tid = threadIdx.x, lane = tid & 31, w = tid >> 5;
    int gr = lane >> 2, lq = lane & 3;
    int m0w = (w >> 2) * 64, n0w = (w & 3) * 32;
    unsigned lA = laneA_off(lane, 144), lB = laneB_off(lane, 144);
    int arow = blockIdx.y * 128;
    int ncol = blockIdx.x * 128;
    int wrow = (remap && ncol >= 512) ? ncol + 512 : ncol;
    const __nv_bfloat16* A1b = A1 + (size_t)arow * 512;
    const __nv_bfloat16* A2b = A2 + (size_t)arow * 512;
    const __nv_bfloat16* W1b = W1 + (size_t)wrow * 512;
    const __nv_bfloat16* W2b = W2 + (size_t)ncol * 512;
    int lr0 = tid >> 3, lcs = (tid & 7) * 8;

    float c[4][4][4];
#pragma unroll
    for (int i = 0; i < 4; i++)
#pragma unroll
        for (int j = 0; j < 4; j++)
#pragma unroll
            for (int q = 0; q < 4; q++) c[i][j][q] = 0.f;

    int nsteps = K / 64;
    // preload stage 0
    {
        __nv_bfloat16* sA = (__nv_bfloat16*)gsm;
        __nv_bfloat16* sB = (__nv_bfloat16*)(gsm + 4608);
#pragma unroll
        for (int q = 0; q < 4; q++) {
            int r = lr0 + q * 32;
            cp16(sA + r * 72 + lcs, A1b + (size_t)r * 512 + lcs);
            cp16(sB + r * 72 + lcs, W1b + (size_t)r * 512 + lcs);
        }
        cp_commit();
    }

    for (int kstep = 0; kstep < nsteps; kstep++) {
        cp_wait0();
        __syncthreads();
        if (kstep + 1 < nsteps) {
            int k0 = (kstep + 1) * 64;
            const __nv_bfloat16* As = (k0 < 512) ? A1b + k0 : A2b + (k0 - 512);
            const __nv_bfloat16* Ws = (k0 < 512) ? W1b + k0 : W2b + (k0 - 512);
            int st = (kstep + 1) & 1;
            __nv_bfloat16* sA = (__nv_bfloat16*)(gsm + st * 9216);
            __nv_bfloat16* sB = (__nv_bfloat16*)(gsm + st * 9216 + 4608);
#pragma unroll
            for (int q = 0; q < 4; q++) {
                int r = lr0 + q * 32;
                cp16(sA + r * 72 + lcs, As + (size_t)r * 512 + lcs);
                cp16(sB + r * 72 + lcs, Ws + (size_t)r * 512 + lcs);
            }
            cp_commit();
        }
        unsigned Au = s2u(gsm + (kstep & 1) * 9216);
        unsigned Bu = Au + 4608 * 4;
#pragma unroll
        for (int ksh = 0; ksh < 64; ksh += 16) {
            unsigned af[4][4], bf[4][2];
#pragma unroll
            for (int ma = 0; ma < 4; ma++)
                ldm4(af[ma][0], af[ma][1], af[ma][2], af[ma][3],
                     Au + (m0w + ma * 16) * 144 + lA + ksh * 2);
#pragma unroll
            for (int nbp = 0; nbp < 2; nbp++)
                ldm4(bf[2 * nbp][0], bf[2 * nbp][1], bf[2 * nbp + 1][0], bf[2 * nbp + 1][1],
                     Bu + (n0w + nbp * 16) * 144 + lB + ksh * 2);
#pragma unroll
            for (int ma = 0; ma < 4; ma++)
#pragma unroll
                for (int nb = 0; nb < 4; nb++) mma16(c[ma][nb], af[ma], bf[nb]);
        }
    }
    int row0 = arow + m0w;
    int col0 = wrow + n0w;
#pragma unroll
    for (int ma = 0; ma < 4; ma++)
#pragma unroll
        for (int nb = 0; nb < 4; nb++) {
            int r = row0 + ma * 16 + gr;
            int cc = col0 + nb * 8 + 2 * lq;
            if (Cb) {
                Cb[(size_t)r * ldcw + (cc >> 1)] = pk2(c[ma][nb][0], c[ma][nb][1]);
                Cb[(size_t)(r + 8) * ldcw + (cc >> 1)] = pk2(c[ma][nb][2], c[ma][nb][3]);
            } else {
                float2 v0 = make_float2(c[ma][nb][0], c[ma][nb][1]);
                float2 v1 = make_float2(c[ma][nb][2], c[ma][nb][3]);
                float bx = bias[cc], by = bias[cc + 1];
                v0.x += bx; v0.y += by; v1.x += bx; v1.y += by;
                *(float2*)&Cf[(size_t)r * ldc + cc] = v0;
                *(float2*)&Cf[(size_t)(r + 8) * ldc + cc] = v1;
            }
        }
}

// ---------------------------------------------------------------------------
// attention stats: per (64-row q-tile, head), 128 threads = 4 warps.
// K chunks via cp.async double-buffer (no register staging).
// Dyn smem: Q[64*36w] + 2*K[64*36w] = 27648 B.
// ---------------------------------------------------------------------------
__global__ void __launch_bounds__(128) attn_stats(
    const unsigned* __restrict__ qkvb, const float* __restrict__ topo,
    float2* __restrict__ stats) {
    extern __shared__ unsigned sm[];
    unsigned* Qs = sm;                          // 64*36
    unsigned* Kb[2] = {sm + 2304, sm + 2304 + 2304};

    int q0 = blockIdx.x * 64;
    int head = blockIdx.y;
    int b = head >> 3, h = head & 7;
    int tid = threadIdx.x, lane = tid & 31, w = tid >> 5;   // w 0..3
    int lq = lane & 3;
    unsigned lA = laneA_off(lane, 144), lB = laneB_off(lane, 144);
    int gr = lane >> 2;
    int r0 = w * 16 + gr, r1 = r0 + 8;
    const __nv_bfloat16* qkvh = (const __nv_bfloat16*)qkvb;
    const __nv_bfloat16* qbase = qkvh + (size_t)b * 512 * 1536 + h * 64;
    const __nv_bfloat16* kbase = qbase + 512;
    const float scale = 0.125f;
    const float* topo0 = topo + (size_t)(q0 + r0) * 512;
    const float* topo1 = topo + (size_t)(q0 + r1) * 512;

    // Q tile (regular stores; visible after first top-of-loop sync)
#pragma unroll
    for (int q = 0; q < 8; q++) {
        int i = tid + q * 128;
        int r = i >> 4, c4 = (i & 15) * 4;
        *(uint2*)&Qs[r * 36 + c4 / 2] = *(const uint2*)(qbase + (size_t)(q0 + r) * 1536 + c4);
    }
    // preload K[0] via cp.async: 64 rows x 8 segs, 4 per thread
    {
        __nv_bfloat16* sK = (__nv_bfloat16*)Kb[0];
#pragma unroll
        for (int q = 0; q < 4; q++) {
            int id = tid + q * 128;
            int r = id >> 3, seg = id & 7;
            cp16(sK + r * 72 + seg * 8, kbase + (size_t)r * 1536 + seg * 8);
        }
        cp_commit();
    }
    unsigned Qu = s2u(Qs) + (w * 16) * 144 + lA;

    float m0 = -1e30f, m1 = -1e30f, s0 = 0.f, s1 = 0.f;
    for (int nc = 0; nc < 8; nc++) {
        cp_wait0();
        __syncthreads();
        if (nc < 7) {
            __nv_bfloat16* sK = (__nv_bfloat16*)Kb[(nc + 1) & 1];
#pragma unroll
            for (int q = 0; q < 4; q++) {
                int id = tid + q * 128;
                int r = id >> 3, seg = id & 7;
                cp16(sK + r * 72 + seg * 8,
                     kbase + (size_t)((nc + 1) * 64 + r) * 1536 + seg * 8);
            }
            cp_commit();
        }
        unsigned Ku = s2u(Kb[nc & 1]) + lB;
        float c[8][4];
#pragma unroll
        for (int j = 0; j < 8; j++)
#pragma unroll
            for (int q = 0; q < 4; q++) c[j][q] = 0.f;
#pragma unroll
        for (int ksh = 0; ksh < 64; ksh += 16) {
            unsigned a[4];
            ldm4(a[0], a[1], a[2], a[3], Qu + ksh * 2);
            unsigned bb[8][2];
#pragma unroll
            for (int nbp = 0; nbp < 4; nbp++)
                ldm4(bb[2 * nbp][0], bb[2 * nbp][1], bb[2 * nbp + 1][0], bb[2 * nbp + 1][1],
                     Ku + nbp * 16 * 144 + ksh * 2);
#pragma unroll
            for (int nb = 0; nb < 8; nb++) mma16(c[nb], a, bb[nb]);
        }
        float tm0 = -1e30f, tm1 = -1e30f;
        float v[8][4];
#pragma unroll
        for (int nb = 0; nb < 8; nb++) {
            int gc = nc * 64 + nb * 8 + 2 * lq;
            float2 t0 = *(const float2*)&topo0[gc];
            float2 t1 = *(const float2*)&topo1[gc];
            v[nb][0] = c[nb][0] * scale + t0.x;
            v[nb][1] = c[nb][1] * scale + t0.y;
            v[nb][2] = c[nb][2] * scale + t1.x;
            v[nb][3] = c[nb][3] * scale + t1.y;
            tm0 = fmaxf(tm0, fmaxf(v[nb][0], v[nb][1]));
            tm1 = fmaxf(tm1, fmaxf(v[nb][2], v[nb][3]));
        }
        tm0 = fmaxf(tm0, __shfl_xor_sync(0xffffffffu, tm0, 1));
        tm0 = fmaxf(tm0, __shfl_xor_sync(0xffffffffu, tm0, 2));
        tm1 = fmaxf(tm1, __shfl_xor_sync(0xffffffffu, tm1, 1));
        tm1 = fmaxf(tm1, __shfl_xor_sync(0xffffffffu, tm1, 2));
        float nm0 = fmaxf(m0, tm0), nm1 = fmaxf(m1, tm1);
        float ps0 = 0.f, ps1 = 0.f;
#pragma unroll
        for (int nb = 0; nb < 8; nb++) {
            ps0 += __expf(v[nb][0] - nm0) + __expf(v[nb][1] - nm0);
            ps1 += __expf(v[nb][2] - nm1) + __expf(v[nb][3] - nm1);
        }
        ps0 += __shfl_xor_sync(0xffffffffu, ps0, 1);
        ps0 += __shfl_xor_sync(0xffffffffu, ps0, 2);
        ps1 += __shfl_xor_sync(0xffffffffu, ps1, 1);
        ps1 += __shfl_xor_sync(0xffffffffu, ps1, 2);
        s0 = s0 * __expf(m0 - nm0) + ps0;
        s1 = s1 * __expf(m1 - nm1) + ps1;
        m0 = nm0; m1 = nm1;
        __syncthreads();   // all warps done with Kb[nc&1] before it is refilled
    }
    if (lq == 0) {
        stats[(size_t)head * 512 + q0 + r0] = make_float2(m0, 1.0f / s0);
        stats[(size_t)head * 512 + q0 + r1] = make_float2(m1, 1.0f / s1);
    }
}

// ---------------------------------------------------------------------------
// attention main: recompute S, normalize with stats, write attn (streaming),
// PV with A from S-accum registers and B via ldmatrix.trans on V[k][n].
// K and V chunks via cp.async double-buffer. Block = (128 q-rows, head).
// Dyn smem: Q[128*36] + 2*K[64*36] + 2*V[64*36] = 55296 B
// ---------------------------------------------------------------------------
__global__ void __launch_bounds__(256) attn_main(
    const unsigned* __restrict__ qkvb, const float* __restrict__ topo,
    const float2* __restrict__ stats,
    float* __restrict__ attn, unsigned* __restrict__ ztb) {
    extern __shared__ unsigned sm[];
    unsigned* Qs = sm;                          // 128*36
    unsigned* Kb[2] = {sm + 4608, sm + 4608 + 2304};
    unsigned* Vb[2] = {sm + 9216, sm + 9216 + 2304};   // [k][n] pitch 36 words

    int q0 = blockIdx.x * 128;
    int head = blockIdx.y;
    int b = head >> 3, h = head & 7;
    int tid = threadIdx.x, lane = tid & 31, w = tid >> 5;
    int gr = lane >> 2, lq = lane & 3;
    unsigned lA = laneA_off(lane, 144), lB = laneB_off(lane, 144);
    int r0 = w * 16 + gr, r1 = r0 + 8;
    const __nv_bfloat16* qkvh = (const __nv_bfloat16*)qkvb;
    const __nv_bfloat16* qbase = qkvh + (size_t)b * 512 * 1536 + h * 64;
    const __nv_bfloat16* kbase = qbase + 512;
    const __nv_bfloat16* vbase = qbase + 1024;
    const float scale = 0.125f;
    const float* topo0 = topo + (size_t)(q0 + r0) * 512;
    const float* topo1 = topo + (size_t)(q0 + r1) * 512;
    float2 st0 = stats[(size_t)head * 512 + q0 + r0];
    float2 st1 = stats[(size_t)head * 512 + q0 + r1];
    float m0 = st0.x, inv0 = st0.y, m1 = st1.x, inv1 = st1.y;

    // Q tile
#pragma unroll
    for (int q = 0; q < 8; q++) {
        int i = tid + q * 256;
        int r = i >> 4, c4 = (i & 15) * 4;
        *(uint2*)&Qs[r * 36 + c4 / 2] = *(const uint2*)(qbase + (size_t)(q0 + r) * 1536 + c4);
    }
    // preload K[0], V[0] via cp.async: 64 rows x 8 segs each, 2+2 per thread
    {
        __nv_bfloat16* sK = (__nv_bfloat16*)Kb[0];
        __nv_bfloat16* sV = (__nv_bfloat16*)Vb[0];
#pragma unroll
        for (int q = 0; q < 2; q++) {
            int id = tid + q * 256;
            int r = id >> 3, seg = id & 7;
            cp16(sK + r * 72 + seg * 8, kbase + (size_t)r * 1536 + seg * 8);
            cp16(sV + r * 72 + seg * 8, vbase + (size_t)r * 1536 + seg * 8);
        }
        cp_commit();
    }
    unsigned Qu = s2u(Qs) + (w * 16) * 144 + lA;

    float z[8][4];
#pragma unroll
    for (int j = 0; j < 8; j++)
#pragma unroll
        for (int q = 0; q < 4; q++) z[j][q] = 0.f;
    float* attn_base = attn + ((size_t)head * 512 + q0) * 512;

    for (int kc = 0; kc < 8; kc++) {
        cp_wait0();
        __syncthreads();
        if (kc < 7) {
            __nv_bfloat16* sK = (__nv_bfloat16*)Kb[(kc + 1) & 1];
            __nv_bfloat16* sV = (__nv_bfloat16*)Vb[(kc + 1) & 1];
#pragma unroll
            for (int q = 0; q < 2; q++) {
                int id = tid + q * 256;
                int r = id >> 3, seg = id & 7;
                cp16(sK + r * 72 + seg * 8,
                     kbase + (size_t)((kc + 1) * 64 + r) * 1536 + seg * 8);
                cp16(sV + r * 72 + seg * 8,
                     vbase + (size_t)((kc + 1) * 64 + r) * 1536 + seg * 8);
            }
            cp_commit();
        }
        unsigned Ku = s2u(Kb[kc & 1]) + lB;
        unsigned Vu = s2u(Vb[kc & 1]) + lA;
        // recompute S chunk
        float c[8][4];
#pragma unroll
        for (int j = 0; j < 8; j++)
#pragma unroll
            for (int q = 0; q < 4; q++) c[j][q] = 0.f;
#pragma unroll
        for (int ksh = 0; ksh < 64; ksh += 16) {
            unsigned a[4];
            ldm4(a[0], a[1], a[2], a[3], Qu + ksh * 2);
            unsigned bb[8][2];
#pragma unroll
            for (int nbp = 0; nbp < 4; nbp++)
                ldm4(bb[2 * nbp][0], bb[2 * nbp][1], bb[2 * nbp + 1][0], bb[2 * nbp + 1][1],
                     Ku + nbp * 16 * 144 + ksh * 2);
#pragma unroll
            for (int nb = 0; nb < 8; nb++) mma16(c[nb], a, bb[nb]);
        }
        // normalize + write attn (streaming)
#pragma unroll
        for (int nb = 0; nb < 8; nb++) {
            int gc = kc * 64 + nb * 8 + 2 * lq;
            float2 t0 = *(const float2*)&topo0[gc];
            float2 t1 = *(const float2*)&topo1[gc];
            c[nb][0] = __expf(c[nb][0] * scale + t0.x - m0) * inv0;
            c[nb][1] = __expf(c[nb][1] * scale + t0.y - m0) * inv0;
            c[nb][2] = __expf(c[nb][2] * scale + t1.x - m1) * inv1;
            c[nb][3] = __expf(c[nb][3] * scale + t1.y - m1) * inv1;
            __stcs((float2*)&attn_base[(size_t)r0 * 512 + gc], make_float2(c[nb][0], c[nb][1]));
            __stcs((float2*)&attn_base[(size_t)r1 * 512 + gc], make_float2(c[nb][2], c[nb][3]));
        }
        // PV: A from S-accum registers; B via ldmatrix.trans on V[k][n]
#pragma unroll
        for (int kb = 0; kb < 4; kb++) {
            unsigned pa[4];
            pa[0] = pk2(c[2 * kb][0], c[2 * kb][1]);
            pa[1] = pk2(c[2 * kb][2], c[2 * kb][3]);
            pa[2] = pk2(c[2 * kb + 1][0], c[2 * kb + 1][1]);
            pa[3] = pk2(c[2 * kb + 1][2], c[2 * kb + 1][3]);
            unsigned vb[8][2];
#pragma unroll
            for (int nbp = 0; nbp < 4; nbp++)
                ldm4t(vb[2 * nbp][0], vb[2 * nbp][1], vb[2 * nbp + 1][0], vb[2 * nbp + 1][1],
                      Vu + kb * 16 * 144 + nbp * 32);
#pragma unroll
            for (int nb = 0; nb < 8; nb++) mma16(z[nb], pa, vb[nb]);
        }
        __syncthreads();   // all warps done with buffers before refill lands next iter
    }
    int orow = b * 512 + q0 + r0;
#pragma unroll
    for (int nb = 0; nb < 8; nb++) {
        int col = h * 64 + nb * 8 + 2 * lq;
        ztb[(size_t)orow * 256 + (col >> 1)] = pk2(z[nb][0], z[nb][1]);
        ztb[(size_t)(orow + 8) * 256 + (col >> 1)] = pk2(z[nb][2], z[nb][3]);
    }
}

// ---------------------------------------------------------------------------
extern "C" void kernel_launch(void* const* d_in, const int* in_sizes, int n_in,
                              void* d_out, int out_size) {
    const float* x       = (const float*)d_in[0];
    const float* x_vel   = (const float*)d_in[1];
    const float* topo    = (const float*)d_in[2];
    const float* W_qkv   = (const float*)d_in[3];
    const float* W_vproj = (const float*)d_in[4];
    const float* W_proj  = (const float*)d_in[5];
    const float* b_proj  = (const float*)d_in[6];

    float* out    = (float*)d_out;
    float* z_man  = out;                                   // 32*512*513
    float* attn   = out + (size_t)BB * JJ * (EE + 1);      // 32*8*512*512
    float* x_tan  = attn + (size_t)BB * HH * JJ * JJ;      // 32*512*512

    void *pq, *pxt, *pvel, *pzt, *pw, *pz2, *pst;
    cudaGetSymbolAddress(&pq, g_qkv_bf);
    cudaGetSymbolAddress(&pxt, g_xt_bf);
    cudaGetSymbolAddress(&pvel, g_vel_bf);
    cudaGetSymbolAddress(&pzt, g_zt_bf);
    cudaGetSymbolAddress(&pw, g_w_bf);
    cudaGetSymbolAddress(&pz2, g_ztan2);
    cudaGetSymbolAddress(&pst, g_stats);
    unsigned* qkvb = (unsigned*)pq;
    unsigned* xtb  = (unsigned*)pxt;
    unsigned* velb = (unsigned*)pvel;
    unsigned* ztb  = (unsigned*)pzt;
    unsigned* wqkvb   = (unsigned*)pw;
    unsigned* wvprojb = wqkvb + 393216;
    unsigned* wprojb  = wvprojb + 131072;
    float* ztan2 = (float*)pz2;
    float2* stats = (float2*)pst;

    const int gemm_smem = 73728;
    const int stats_smem = 27648;
    const int main_smem = 55296;
    static int attr_set = 0;
    if (!attr_set) {
        cudaFuncSetAttribute(gemm_bf, cudaFuncAttributeMaxDynamicSharedMemorySize, gemm_smem);
        cudaFuncSetAttribute(attn_stats, cudaFuncAttributeMaxDynamicSharedMemorySize, stats_smem);
        cudaFuncSetAttribute(attn_main, cudaFuncAttributeMaxDynamicSharedMemorySize, main_smem);
        attr_set = 1;
    }

    // 1. fused prep: log-map + vel staging + weight conversion
    prep_kernel<<<MROWS + 5120, 128>>>(x, x_vel, x_tan, xtb, velb,
                                       W_qkv, W_vproj, W_proj, wqkvb);

    const __nv_bfloat16* xth = (const __nv_bfloat16*)xtb;
    const __nv_bfloat16* velh = (const __nv_bfloat16*)velb;
    const __nv_bfloat16* wqkvh = (const __nv_bfloat16*)wqkvb;
    const __nv_bfloat16* wvprojh = (const __nv_bfloat16*)wvprojb;
    const __nv_bfloat16* wprojh = (const __nv_bfloat16*)wprojb;
    const __nv_bfloat16* zth = (const __nv_bfloat16*)ztb;

    // 2. q|v slabs (N=1024 remapped), K=512
    {
        dim3 g(8, MROWS / 128);
        gemm_bf<<<g, 256, gemm_smem>>>(xth, xth, wqkvh, wqkvh, 512, 1,
                                       qkvb, 768, nullptr, 0, nullptr);
    }
    // 3. k slab: concat-K (x_tan|v_tan @ Wk|Wvproj), K=1024
    {
        dim3 g(4, MROWS / 128);
        gemm_bf<<<g, 256, gemm_smem>>>(xth, velh, wqkvh + 512 * 512, wvprojh, 1024, 0,
                                       qkvb + 256, 768, nullptr, 0, nullptr);
    }
    // 4. softmax stats
    {
        dim3 g(8, BB * HH);
        attn_stats<<<g, 128, stats_smem>>>(qkvb, topo, stats);
    }
    // 5. attn + PV
    {
        dim3 g(4, BB * HH);
        attn_main<<<g, 256, main_smem>>>(qkvb, topo, stats, attn, ztb);
    }
    // 6. out-proj
    {
        dim3 g(4, MROWS / 128);
        gemm_bf<<<g, 256, gemm_smem>>>(zth, zth, wprojh, wprojh, 512, 0,
                                       nullptr, 0, ztan2, 512, b_proj);
    }
    // 7. exp-map
    expmap_kernel<<<MROWS, 128>>>(ztan2, z_man);
}